// round 4
// baseline (speedup 1.0000x reference)
#include <cuda_runtime.h>
#include <cuda_fp16.h>

#define I_DIM   128
#define O_DIM   128
#define G_NUM   128
#define G1      129
#define B_DIM   8192
#define C_CHUNKS 4
#define ICHUNK  (I_DIM / C_CHUNKS)   /* 32 */
#define BT      256                  /* batch columns per block */
#define NBT     (B_DIM / BT)         /* 32 */
#define THREADS 512
#define NWARP   (THREADS / 32)       /* 16 */
#define BPW     (BT / NWARP)         /* 16 batch columns per warp */
#define ROW_U2  (O_DIM / 4)          /* 32 uint2 per 256B fp16 row */

// Static device scratch (allocation-free per harness rules)
__device__ __align__(16) __half g_P2h[(size_t)I_DIM * G1 * O_DIM]; // [i][g][o] 4.2MB
__device__ float g_partial[C_CHUNKS][B_DIM][O_DIM];                // [c][b][o] 16MB

// ---------------------------------------------------------------------------
// Kernel 1: transpose+quantize P[g][o][i] (fp32) -> P2h[i][g][o] (fp16).
// Block = (one g, 32 i's), 128 threads. Reads are LDG.128 (8 per thread ->
// deep MLP, DRAM latency covered); smem STS.32 conflict-free (stride 33).
// Writes: half2 coalesced.
// ---------------------------------------------------------------------------
__global__ void transpose_kernel(const float* __restrict__ P) {
    __shared__ float tile[O_DIM][33];
    const int g  = blockIdx.y;           // 0..128
    const int i0 = blockIdx.x * 32;      // 0..96
    const int t = threadIdx.x, w = t >> 5, lane = t & 31;
    const int quad = lane >> 3;          // 0..3  (row within group of 4)
    const int sub  = lane & 7;           // 0..7  (float4 within 32-float row)

    const float4* src = (const float4*)(P + (size_t)g * O_DIM * I_DIM + i0);
    float4 v[8];
#pragma unroll
    for (int r = 0; r < 8; r++) {
        int o = w * 32 + r * 4 + quad;
        v[r] = src[(size_t)o * (I_DIM / 4) + sub];
    }
#pragma unroll
    for (int r = 0; r < 8; r++) {
        int o = w * 32 + r * 4 + quad;
        tile[o][sub * 4 + 0] = v[r].x;   // bank = (o + 4*sub + k) % 32:
        tile[o][sub * 4 + 1] = v[r].y;   // conflict-free per STS
        tile[o][sub * 4 + 2] = v[r].z;
        tile[o][sub * 4 + 3] = v[r].w;
    }
    __syncthreads();

    const int op = t & 63;          // o-pair index
    const int il = t >> 6;          // 0..1
    __half2* dst = (__half2*)g_P2h;
#pragma unroll
    for (int r = 0; r < 16; r++) {
        int i = il + 2 * r;
        dst[((size_t)(i0 + i) * G1 + g) * (O_DIM / 2) + op] =
            __floats2half2_rn(tile[2 * op][i], tile[2 * op + 1][i]);
    }
}

// ---------------------------------------------------------------------------
// Kernel 2: gather + lerp (half2) + accumulate. Block = 256 b x 32 i.
// Warp handles 16 batch cols; lane covers 4 outputs.
// ---------------------------------------------------------------------------
__global__ __launch_bounds__(THREADS, 1)
void main_kernel(const float* __restrict__ x,
                 const float* __restrict__ borders,
                 const float* __restrict__ invl) {
    __shared__ __align__(16) unsigned int s_gd[ICHUNK][BT];  // 32 KB
    __shared__ float s_b[G1];
    __shared__ float s_il[G_NUM];

    const int t     = threadIdx.x;
    const int btile = blockIdx.x;    // 0..31
    const int chunk = blockIdx.y;    // 0..3
    const int b0    = btile * BT;
    const int i0    = chunk * ICHUNK;

    if (t < G1)    s_b[t]  = borders[t];
    if (t < G_NUM) s_il[t] = invl[t];
    __syncthreads();

    // Phase 1: bucket index g + interpolation weight d, packed (g | half(d)<<16)
    {
        const int bl    = t & (BT - 1);
        const int ibase = t >> 8;           // 0..1
#pragma unroll
        for (int p = 0; p < ICHUNK / 2; p++) {
            int il = ibase + 2 * p;
            float xv = x[(size_t)(i0 + il) * B_DIM + b0 + bl];
            float e  = __expf(-fabsf(xv));
            float cdf = (xv > 0.f) ? (1.f - 0.5f * e) : (0.5f * e);
            int g = (int)(cdf * (float)G_NUM);
            g = min(max(g, 0), G_NUM - 1);
            float d = (xv - s_b[g]) * s_il[g];
            unsigned db = (unsigned)__half_as_ushort(__float2half_rn(d));
            s_gd[il][bl] = (unsigned)g | (db << 16);
        }
    }
    __syncthreads();

    const int w    = t >> 5;
    const int lane = t & 31;
    const int wb   = w * BPW;

    const __half2 one2 = __floats2half2_rn(1.f, 1.f);
    const __half2 z2   = __floats2half2_rn(0.f, 0.f);
    const uint2* __restrict__ P2v = (const uint2*)g_P2h;

    float4 accF[BPW];
#pragma unroll
    for (int j = 0; j < BPW; j++) accF[j] = make_float4(0.f, 0.f, 0.f, 0.f);

    for (int iiB = 0; iiB < ICHUNK; iiB += 4) {
        __half2 a0[BPW], a1[BPW];
#pragma unroll
        for (int j = 0; j < BPW; j++) { a0[j] = z2; a1[j] = z2; }

#pragma unroll
        for (int u = 0; u < 4; u++) {
            const int ii = iiB + u;
            const uint2* slice = P2v + (size_t)(i0 + ii) * (G1 * ROW_U2);
#pragma unroll
            for (int jq = 0; jq < 4; jq++) {
                // one LDS.128 fetches descriptors for 4 batch columns
                uint4 g4 = *(const uint4*)&s_gd[ii][wb + jq * 4];
                unsigned vs0 = g4.x, vs1 = g4.y, vs2 = g4.z, vs3 = g4.w;
#pragma unroll
                for (int m = 0; m < 4; m++) {
                    const int j = jq * 4 + m;
                    unsigned v  = (m == 0) ? vs0 : (m == 1) ? vs1
                                : (m == 2) ? vs2 : vs3;
                    unsigned gi = v & 0xFFu;
                    unsigned dd = __byte_perm(v, v, 0x3232);
                    __half2 d2  = *(__half2*)&dd;
                    __half2 w2  = __hsub2(one2, d2);
                    const uint2* rowp = slice + gi * ROW_U2 + lane;
                    uint2 A  = __ldg(rowp);             // row g   (256B coalesced)
                    uint2 Bv = __ldg(rowp + ROW_U2);    // row g+1 (adjacent)
                    a0[j] = __hfma2(w2, *(__half2*)&A.x,  a0[j]);
                    a0[j] = __hfma2(d2, *(__half2*)&Bv.x, a0[j]);
                    a1[j] = __hfma2(w2, *(__half2*)&A.y,  a1[j]);
                    a1[j] = __hfma2(d2, *(__half2*)&Bv.y, a1[j]);
                }
            }
        }

        // flush half2 partials into fp32 accumulators every 4 slices
#pragma unroll
        for (int j = 0; j < BPW; j++) {
            float2 p0 = __half22float2(a0[j]);
            float2 p1 = __half22float2(a1[j]);
            accF[j].x += p0.x; accF[j].y += p0.y;
            accF[j].z += p1.x; accF[j].w += p1.y;
        }
        // keep all 16 warps on the same ~132KB 4-slice window (L1 reuse)
        __syncthreads();
    }

    // Coalesced float4 stores into [c][b][o] scratch.
#pragma unroll
    for (int j = 0; j < BPW; j++) {
        float4* dst = (float4*)&g_partial[chunk][b0 + wb + j][0];
        dst[lane] = accF[j];
    }
}

// ---------------------------------------------------------------------------
// Kernel 3: sum the C partials and transpose [b][o] -> out[o][b].
// ---------------------------------------------------------------------------
__global__ void reduce_kernel(float* __restrict__ out) {
    __shared__ float4 tile[32][33];
    const int b0 = blockIdx.x * 32;
    const int tx = threadIdx.x, ty = threadIdx.y;   // (32, 8)
    const size_t cstride = (size_t)B_DIM * (O_DIM / 4);   // in float4

    const float4* pbase = (const float4*)&g_partial[0][0][0];
#pragma unroll
    for (int r = 0; r < 4; r++) {
        int b = ty + r * 8;
        const float4* p = pbase + (size_t)(b0 + b) * (O_DIM / 4) + tx;
        float4 s = p[0];
#pragma unroll
        for (int c = 1; c < C_CHUNKS; c++) {
            float4 v = p[c * cstride];
            s.x += v.x; s.y += v.y; s.z += v.z; s.w += v.w;
        }
        tile[b][tx] = s;
    }
    __syncthreads();

    const float* tf = (const float*)tile;   // row stride = 33*4 = 132 floats
#pragma unroll
    for (int r = 0; r < 16; r++) {
        int o = ty + r * 8;
        out[(size_t)o * B_DIM + b0 + tx] = tf[tx * 132 + o];
    }
}

// ---------------------------------------------------------------------------
extern "C" void kernel_launch(void* const* d_in, const int* in_sizes, int n_in,
                              void* d_out, int out_size) {
    const float* x       = (const float*)d_in[0];   // [128, 8192]
    const float* P       = (const float*)d_in[1];   // [129, 128, 128]
    const float* borders = (const float*)d_in[2];   // [129]
    const float* invl    = (const float*)d_in[3];   // [128]
    float*       out     = (float*)d_out;           // [128, 8192]

    transpose_kernel<<<dim3(4, G1), 128>>>(P);
    main_kernel<<<dim3(NBT, C_CHUNKS), THREADS>>>(x, borders, invl);
    reduce_kernel<<<B_DIM / 32, dim3(32, 8)>>>(out);
}